// round 16
// baseline (speedup 1.0000x reference)
#include <cuda_runtime.h>
#include <cuda_bf16.h>
#include <cstdint>

// BNB 8-bit embedding dequant-on-gather (sm_103a), R16.
// Identities: row base = q_idx + id*1024; scale = absmax[id>>2].
//
// R15 core (LDG.256 evict_last reads, STG.256 .wt writes, depth-2 register
// pipeline) scaled to 16 tokens/CTA (grid 2048): two 128-lane halves, 8 rows
// per half, software-pipelined depth 2. Halves per-CTA fixed overhead
// (codebook fill, id stage, barrier) vs R15 while keeping live registers
// bounded (two row buffers) — no spill (R11 lesson).

#define TOKENS_PER_CTA 16
#define ROWS_PER_HALF  8
#define ROW_F 1024

__device__ __forceinline__ void ldg_nc_el_v8(const int* p, uint32_t r[8]) {
    asm volatile("ld.global.nc.L2::evict_last.v8.b32 "
                 "{%0,%1,%2,%3,%4,%5,%6,%7}, [%8];"
                 : "=r"(r[0]), "=r"(r[1]), "=r"(r[2]), "=r"(r[3]),
                   "=r"(r[4]), "=r"(r[5]), "=r"(r[6]), "=r"(r[7])
                 : "l"(p));
}

__device__ __forceinline__ void stg_wt_v8(float* p, const float o[8]) {
    asm volatile("st.global.wt.v8.f32 [%0], {%1,%2,%3,%4,%5,%6,%7,%8};"
                 :: "l"(p),
                    "f"(o[0]), "f"(o[1]), "f"(o[2]), "f"(o[3]),
                    "f"(o[4]), "f"(o[5]), "f"(o[6]), "f"(o[7])
                 : "memory");
}

__global__ __launch_bounds__(256)
void bnb8bit_embedding_kernel(const int* __restrict__ x,
                              const int* __restrict__ q_idx,
                              const float* __restrict__ absmax,
                              const float* __restrict__ code,
                              float* __restrict__ out,
                              int n_tokens) {
    __shared__ float s_code[256];
    __shared__ int   s_ids[TOKENS_PER_CTA];

    const int t = threadIdx.x;
    s_code[t] = code[t];

    const int base = blockIdx.x * TOKENS_PER_CTA;
    if (t < TOKENS_PER_CTA) {
        int tok = base + t;
        s_ids[t] = (tok < n_tokens) ? x[tok] : 0;
    }
    __syncthreads();

    const int half = t >> 7;              // which group of 8 tokens
    const int lane = t & 127;             // 32B segment within the row
    const int toff = half * ROWS_PER_HALF;

    if (base + TOKENS_PER_CTA <= n_tokens) {
        // Depth-2 software pipeline over 8 rows; two register row buffers.
        uint32_t va[8], vb[8];
        float    o[8];

        const int id0 = s_ids[toff + 0];
        const int id1 = s_ids[toff + 1];
        ldg_nc_el_v8(q_idx + (size_t)id0 * ROW_F + lane * 8, va);
        ldg_nc_el_v8(q_idx + (size_t)id1 * ROW_F + lane * 8, vb);

        #pragma unroll
        for (int i = 0; i < ROWS_PER_HALF; i++) {
            uint32_t* vcur = (i & 1) ? vb : va;
            uint32_t* vnxt = (i & 1) ? va : vb;
            const int   id = s_ids[toff + i];
            const float sc = __ldg(absmax + (id >> 2));

            // Launch load for row i+2 into the buffer row i just freed.
            if (i + 2 < ROWS_PER_HALF) {
                const int idn = s_ids[toff + i + 2];
                // vnxt currently holds row i+1's data only when (i+2)&1 != (i+1)&1;
                // buffers alternate: row i in (i&1) buffer, so row i+2 reuses vcur.
            }

            #pragma unroll
            for (int j = 0; j < 8; j++)
                o[j] = s_code[vcur[j]] * sc;

            if (i + 2 < ROWS_PER_HALF) {
                const int idn = s_ids[toff + i + 2];
                ldg_nc_el_v8(q_idx + (size_t)idn * ROW_F + lane * 8, vcur);
            }

            stg_wt_v8(out + (size_t)(base + toff + i) * ROW_F + lane * 8, o);
        }
    } else {
        // Tail path.
        for (int i = 0; i < ROWS_PER_HALF; i++) {
            const int tok = base + toff + i;
            if (tok >= n_tokens) break;
            const int id = s_ids[toff + i];
            const float sc = __ldg(absmax + (id >> 2));
            uint32_t v[8];
            ldg_nc_el_v8(q_idx + (size_t)id * ROW_F + lane * 8, v);
            float o[8];
            #pragma unroll
            for (int j = 0; j < 8; j++)
                o[j] = s_code[v[j]] * sc;
            stg_wt_v8(out + (size_t)tok * ROW_F + lane * 8, o);
        }
    }
}

extern "C" void kernel_launch(void* const* d_in, const int* in_sizes, int n_in,
                              void* d_out, int out_size) {
    const int*   x      = (const int*)d_in[0];
    const int*   q_idx  = (const int*)d_in[1];
    const float* absmax = (const float*)d_in[2];
    const float* code   = (const float*)d_in[3];
    float*       out    = (float*)d_out;

    const int n_tokens = in_sizes[0];   // 8*4096 = 32768
    const int grid = (n_tokens + TOKENS_PER_CTA - 1) / TOKENS_PER_CTA;
    bnb8bit_embedding_kernel<<<grid, 256>>>(x, q_idx, absmax, code, out, n_tokens);
}

// round 17
// speedup vs baseline: 1.0106x; 1.0106x over previous
#include <cuda_runtime.h>
#include <cuda_bf16.h>
#include <cstdint>

// BNB 8-bit embedding dequant-on-gather (sm_103a) — champion artifact (R15).
// Identities: row base = q_idx + id*1024 (chunk*64+local == id)
//             scale    = absmax[id>>2]   ((id>>6)*16 + ((id&63)>>2) == id>>2)
//
// 8 tokens/CTA, 256 threads in two 128-lane halves; per thread a depth-2
// software pipeline of LDG.256 (L2::evict_last) reads and STG.256 (.wt)
// writes. Measured: 38.5us kernel, 5.31 TB/s DRAM (67% of spec) — at the
// random-gather + mixed r/w DRAM ceiling (8 designs all pinned 38.5-40.4us;
// parallelism 10x over Little's-law requirement).

#define TOKENS_PER_CTA 8
#define ROW_F 1024

__device__ __forceinline__ void ldg_nc_el_v8(const int* p, uint32_t r[8]) {
    asm volatile("ld.global.nc.L2::evict_last.v8.b32 "
                 "{%0,%1,%2,%3,%4,%5,%6,%7}, [%8];"
                 : "=r"(r[0]), "=r"(r[1]), "=r"(r[2]), "=r"(r[3]),
                   "=r"(r[4]), "=r"(r[5]), "=r"(r[6]), "=r"(r[7])
                 : "l"(p));
}

__device__ __forceinline__ void stg_wt_v8(float* p, const float o[8]) {
    asm volatile("st.global.wt.v8.f32 [%0], {%1,%2,%3,%4,%5,%6,%7,%8};"
                 :: "l"(p),
                    "f"(o[0]), "f"(o[1]), "f"(o[2]), "f"(o[3]),
                    "f"(o[4]), "f"(o[5]), "f"(o[6]), "f"(o[7])
                 : "memory");
}

__global__ __launch_bounds__(256)
void bnb8bit_embedding_kernel(const int* __restrict__ x,
                              const int* __restrict__ q_idx,
                              const float* __restrict__ absmax,
                              const float* __restrict__ code,
                              float* __restrict__ out,
                              int n_tokens) {
    __shared__ float s_code[256];
    __shared__ int   s_ids[TOKENS_PER_CTA];

    const int t = threadIdx.x;
    s_code[t] = code[t];

    const int base = blockIdx.x * TOKENS_PER_CTA;
    if (t < TOKENS_PER_CTA) {
        int tok = base + t;
        s_ids[t] = (tok < n_tokens) ? x[tok] : 0;
    }
    __syncthreads();

    const int half = t >> 7;        // which group of 4 tokens
    const int lane = t & 127;       // 32B segment within the row
    const int toff = half * 4;

    if (base + TOKENS_PER_CTA <= n_tokens) {
        const int id0 = s_ids[toff + 0];
        const int id1 = s_ids[toff + 1];
        const int id2 = s_ids[toff + 2];
        const int id3 = s_ids[toff + 3];
        const float sc0 = __ldg(absmax + (id0 >> 2));
        const float sc1 = __ldg(absmax + (id1 >> 2));
        const float sc2 = __ldg(absmax + (id2 >> 2));
        const float sc3 = __ldg(absmax + (id3 >> 2));

        uint32_t v0[8], v1[8], v2[8], v3[8];
        float o[8];

        // Prologue: two loads in flight.
        ldg_nc_el_v8(q_idx + (size_t)id0 * ROW_F + lane * 8, v0);
        ldg_nc_el_v8(q_idx + (size_t)id1 * ROW_F + lane * 8, v1);

        // Store 0, load 2.
        #pragma unroll
        for (int j = 0; j < 8; j++) o[j] = s_code[v0[j]] * sc0;
        ldg_nc_el_v8(q_idx + (size_t)id2 * ROW_F + lane * 8, v2);
        stg_wt_v8(out + (size_t)(base + toff + 0) * ROW_F + lane * 8, o);

        // Store 1, load 3.
        #pragma unroll
        for (int j = 0; j < 8; j++) o[j] = s_code[v1[j]] * sc1;
        ldg_nc_el_v8(q_idx + (size_t)id3 * ROW_F + lane * 8, v3);
        stg_wt_v8(out + (size_t)(base + toff + 1) * ROW_F + lane * 8, o);

        // Drain.
        #pragma unroll
        for (int j = 0; j < 8; j++) o[j] = s_code[v2[j]] * sc2;
        stg_wt_v8(out + (size_t)(base + toff + 2) * ROW_F + lane * 8, o);

        #pragma unroll
        for (int j = 0; j < 8; j++) o[j] = s_code[v3[j]] * sc3;
        stg_wt_v8(out + (size_t)(base + toff + 3) * ROW_F + lane * 8, o);
    } else {
        for (int i = 0; i < 4; i++) {
            const int tok = base + toff + i;
            if (tok >= n_tokens) break;
            const int id = s_ids[toff + i];
            const float sc = __ldg(absmax + (id >> 2));
            uint32_t v[8];
            ldg_nc_el_v8(q_idx + (size_t)id * ROW_F + lane * 8, v);
            float o[8];
            #pragma unroll
            for (int j = 0; j < 8; j++)
                o[j] = s_code[v[j]] * sc;
            stg_wt_v8(out + (size_t)tok * ROW_F + lane * 8, o);
        }
    }
}

extern "C" void kernel_launch(void* const* d_in, const int* in_sizes, int n_in,
                              void* d_out, int out_size) {
    const int*   x      = (const int*)d_in[0];
    const int*   q_idx  = (const int*)d_in[1];
    const float* absmax = (const float*)d_in[2];
    const float* code   = (const float*)d_in[3];
    float*       out    = (float*)d_out;

    const int n_tokens = in_sizes[0];   // 8*4096 = 32768
    const int grid = (n_tokens + TOKENS_PER_CTA - 1) / TOKENS_PER_CTA;
    bnb8bit_embedding_kernel<<<grid, 256>>>(x, q_idx, absmax, code, out, n_tokens);
}